// round 1
// baseline (speedup 1.0000x reference)
#include <cuda_runtime.h>

#define NN 512   // nodes
#define NE 512   // edges
#define D  128   // emb dim
#define H  256   // hidden
#define NI 8192  // incidences

// ---------------- scratch (no allocations allowed) ----------------
__device__ float g_eSum[NE * D];
__device__ float g_eCnt[NE];
__device__ float g_hX [NN * H];
__device__ float g_hEb[NE * H];
__device__ int   g_mode;   // 1 = indices are int64, 0 = int32

// ---------------- K0: zero scratch + detect index dtype ----------------
__global__ void k_zero_detect(const void* __restrict__ Ep) {
    int i = blockIdx.x * 256 + threadIdx.x;          // grid covers 66048 = 512*128 + 512
    if (i < NE * D) {
        g_eSum[i] = 0.0f;
    } else {
        int j = i - NE * D;
        if (j < NE) g_eCnt[j] = 0.0f;
    }
    if (blockIdx.x == 0 && threadIdx.x == 0) {
        // If the buffer is really int32, an int64 read combines two indices ->
        // almost surely >= 2^32 (or at least >= NE) for some of the first 32 reads.
        const long long* e64 = (const long long*)Ep;
        int ok = 1;
        #pragma unroll 1
        for (int k = 0; k < 32; k++) {
            long long v = e64[k];
            if (v < 0 || v >= (long long)NE) { ok = 0; break; }
        }
        g_mode = ok;
    }
}

// ---------------- K1: scatter-sum + counts ----------------
__global__ void k_scatter(const float* __restrict__ X,
                          const void* __restrict__ Vp,
                          const void* __restrict__ Ep) {
    int gid = blockIdx.x * 256 + threadIdx.x;        // NI*D threads
    int inc = gid >> 7;
    int d   = gid & 127;
    int v, e;
    if (g_mode) {
        v = (int)((const long long*)Vp)[inc];
        e = (int)((const long long*)Ep)[inc];
    } else {
        v = ((const int*)Vp)[inc];
        e = ((const int*)Ep)[inc];
    }
    atomicAdd(&g_eSum[e * D + d], X[v * D + d]);
    if (d == 0) atomicAdd(&g_eCnt[e], 1.0f);
}

// ---------------- K2: fused GEMM for hX and hEb ----------------
// Rows 0..511  : A = X,                out g_hX  = X @ W1[:, :128].T
// Rows 512..1023: A = eSum/max(cnt,1), out g_hEb = eX @ W1[:, 128:].T + b1
// Block tile 64 rows x 64 h, K chunked by 32, 256 threads, 4x4 per thread.
__global__ void __launch_bounds__(256) k_gemm(const float* __restrict__ X,
                                              const float* __restrict__ W1,
                                              const float* __restrict__ b1) {
    __shared__ float sA[32 * 68];   // [k][row], padded ld=68 (16B aligned, decorrelated banks)
    __shared__ float sB[32 * 68];   // [k][h]
    int tid = threadIdx.x;
    int tx = tid & 15, ty = tid >> 4;
    int h0 = blockIdx.x * 64;
    int r0 = blockIdx.y * 64;
    bool isX = (r0 < NN);
    int koff = isX ? 0 : D;

    float acc[4][4];
    #pragma unroll
    for (int i = 0; i < 4; i++)
        #pragma unroll
        for (int j = 0; j < 4; j++) acc[i][j] = 0.0f;

    for (int k0 = 0; k0 < D; k0 += 32) {
        __syncthreads();
        #pragma unroll
        for (int i = 0; i < 2; i++) {
            int lin = tid + 256 * i;          // 0..511
            int kq  = lin & 7;                // float4 index over k (0..7)
            int row = lin >> 3;               // 0..63
            int gr  = r0 + row;
            float4 f;
            if (isX) {
                f = *(const float4*)(X + gr * D + k0 + kq * 4);
            } else {
                f = *(const float4*)(g_eSum + (gr - NN) * D + k0 + kq * 4);
                float c = g_eCnt[gr - NN];
                float s = 1.0f / fmaxf(c, 1.0f);
                f.x *= s; f.y *= s; f.z *= s; f.w *= s;
            }
            sA[(kq * 4 + 0) * 68 + row] = f.x;
            sA[(kq * 4 + 1) * 68 + row] = f.y;
            sA[(kq * 4 + 2) * 68 + row] = f.z;
            sA[(kq * 4 + 3) * 68 + row] = f.w;

            float4 g = *(const float4*)(W1 + (h0 + row) * (2 * D) + koff + k0 + kq * 4);
            sB[(kq * 4 + 0) * 68 + row] = g.x;
            sB[(kq * 4 + 1) * 68 + row] = g.y;
            sB[(kq * 4 + 2) * 68 + row] = g.z;
            sB[(kq * 4 + 3) * 68 + row] = g.w;
        }
        __syncthreads();

        #pragma unroll
        for (int kk = 0; kk < 32; kk++) {
            float4 a4 = *(float4*)&sA[kk * 68 + 4 * ty];
            float4 b4 = *(float4*)&sB[kk * 68 + 4 * tx];
            float a[4] = {a4.x, a4.y, a4.z, a4.w};
            float b[4] = {b4.x, b4.y, b4.z, b4.w};
            #pragma unroll
            for (int i = 0; i < 4; i++)
                #pragma unroll
                for (int j = 0; j < 4; j++)
                    acc[i][j] = fmaf(a[i], b[j], acc[i][j]);
        }
    }

    #pragma unroll
    for (int i = 0; i < 4; i++) {
        int gr = r0 + 4 * ty + i;
        #pragma unroll
        for (int j = 0; j < 4; j++) {
            int h = h0 + 4 * tx + j;
            if (isX) g_hX[gr * H + h] = acc[i][j];
            else     g_hEb[(gr - NN) * H + h] = acc[i][j] + b1[h];
        }
    }
}

// ---------------- K3: fused relu-dot + sigmoid epilogue ----------------
// out[n,m] = clip(sigmoid( sum_h relu(hX[n,h]+hEb[m,h]) * W2[h] + b2 ))
// 32x32 output tile per CTA, 128 threads, thread tile 2(n) x 4(m), h in 2 chunks of 128.
__global__ void __launch_bounds__(128) k_epi(const float* __restrict__ W2,
                                             const float* __restrict__ b2,
                                             float* __restrict__ out) {
    __shared__ float sX[32 * 132];  // [n][h] padded ld=132 (16B aligned)
    __shared__ float sE[32 * 132];  // [m][h]
    __shared__ float sW[H];
    int tid = threadIdx.x;
    int tx = tid & 7;               // m lane: m = m0 + tx + 8j
    int ty = tid >> 3;              // n lane: n = n0 + ty + 16i
    int m0 = blockIdx.x * 32;
    int n0 = blockIdx.y * 32;

    sW[tid]       = W2[tid];
    sW[tid + 128] = W2[tid + 128];

    float acc[2][4];
    #pragma unroll
    for (int i = 0; i < 2; i++)
        #pragma unroll
        for (int j = 0; j < 4; j++) acc[i][j] = 0.0f;

    for (int hc = 0; hc < H; hc += 128) {
        __syncthreads();
        #pragma unroll
        for (int i = 0; i < 8; i++) {
            int lin = tid + 128 * i;          // 0..1023
            int hq = lin & 31;                // float4 over h
            int r  = lin >> 5;                // 0..31
            *(float4*)&sX[r * 132 + 4 * hq] =
                *(const float4*)(g_hX  + (n0 + r) * H + hc + 4 * hq);
            *(float4*)&sE[r * 132 + 4 * hq] =
                *(const float4*)(g_hEb + (m0 + r) * H + hc + 4 * hq);
        }
        __syncthreads();

        #pragma unroll 4
        for (int h = 0; h < 128; h += 4) {
            float4 w4 = *(float4*)&sW[hc + h];
            float4 x0 = *(float4*)&sX[ty * 132 + h];
            float4 x1 = *(float4*)&sX[(ty + 16) * 132 + h];
            float ws[4] = {w4.x, w4.y, w4.z, w4.w};
            float xs[2][4] = {{x0.x, x0.y, x0.z, x0.w},
                              {x1.x, x1.y, x1.z, x1.w}};
            #pragma unroll
            for (int j = 0; j < 4; j++) {
                float4 e4 = *(float4*)&sE[(tx + 8 * j) * 132 + h];
                float es[4] = {e4.x, e4.y, e4.z, e4.w};
                #pragma unroll
                for (int i = 0; i < 2; i++) {
                    #pragma unroll
                    for (int c = 0; c < 4; c++) {
                        float t = xs[i][c] + es[c];
                        t = fmaxf(t, 0.0f);
                        acc[i][j] = fmaf(t, ws[c], acc[i][j]);
                    }
                }
            }
        }
    }

    float b2v = b2[0];
    #pragma unroll
    for (int i = 0; i < 2; i++) {
        int n = n0 + ty + 16 * i;
        #pragma unroll
        for (int j = 0; j < 4; j++) {
            int m = m0 + tx + 8 * j;
            float lg = acc[i][j] + b2v;
            float p = 1.0f / (1.0f + __expf(-lg));
            p = fminf(fmaxf(p, 1e-6f), 1.0f - 1e-6f);
            out[n * NE + m] = p;
        }
    }
}

// ---------------- launch ----------------
extern "C" void kernel_launch(void* const* d_in, const int* in_sizes, int n_in,
                              void* d_out, int out_size) {
    const float* X  = (const float*)d_in[0];
    const void*  V  = d_in[1];
    const void*  E  = d_in[2];
    const float* W1 = (const float*)d_in[3];
    const float* b1 = (const float*)d_in[4];
    const float* W2 = (const float*)d_in[5];
    const float* b2 = (const float*)d_in[6];
    float* out = (float*)d_out;

    k_zero_detect<<<258, 256>>>(E);                         // 258*256 == 512*128 + 512
    k_scatter<<<(NI * D) / 256, 256>>>(X, V, E);            // 4096 blocks
    k_gemm<<<dim3(H / 64, (NN + NE) / 64), 256>>>(X, W1, b1); // (4,16)
    k_epi<<<dim3(NE / 32, NN / 32), 128>>>(W2, b2, out);    // (16,16)
}

// round 2
// speedup vs baseline: 1.0469x; 1.0469x over previous
#include <cuda_runtime.h>

#define NN 512   // nodes
#define NE 512   // edges
#define D  128   // emb dim
#define H  256   // hidden
#define NI 8192  // incidences

// ---------------- scratch (no allocations allowed) ----------------
__device__ float g_eSum[NE * D];
__device__ float g_eCnt[NE];
__device__ float g_hX [NN * H];
__device__ float g_hEb[NE * H];
__device__ int   g_mode;   // 1 = indices are int64, 0 = int32

// ---------------- f32x2 packed helpers (Blackwell FADD2/FFMA2) ----------------
typedef unsigned long long ull;

__device__ __forceinline__ ull pk2(float lo, float hi) {
    ull r;
    asm("mov.b64 %0, {%1, %2};" : "=l"(r) : "f"(lo), "f"(hi));
    return r;
}
__device__ __forceinline__ ull add2(ull a, ull b) {
    ull r;
    asm("add.rn.f32x2 %0, %1, %2;" : "=l"(r) : "l"(a), "l"(b));
    return r;
}
__device__ __forceinline__ ull fma2(ull a, ull b, ull c) {
    ull r;
    asm("fma.rn.f32x2 %0, %1, %2, %3;" : "=l"(r) : "l"(a), "l"(b), "l"(c));
    return r;
}
__device__ __forceinline__ ull relu2(ull t) {
    float lo, hi;
    asm("mov.b64 {%0, %1}, %2;" : "=f"(lo), "=f"(hi) : "l"(t));
    lo = fmaxf(lo, 0.0f);
    hi = fmaxf(hi, 0.0f);
    return pk2(lo, hi);
}
__device__ __forceinline__ float hsum2(ull t) {
    float lo, hi;
    asm("mov.b64 {%0, %1}, %2;" : "=f"(lo), "=f"(hi) : "l"(t));
    return lo + hi;
}

// ---------------- K0: zero scratch + detect index dtype ----------------
__global__ void k_zero_detect(const void* __restrict__ Ep) {
    int i = blockIdx.x * 256 + threadIdx.x;          // grid covers 66048 = 512*128 + 512
    if (i < NE * D) {
        g_eSum[i] = 0.0f;
    } else {
        int j = i - NE * D;
        if (j < NE) g_eCnt[j] = 0.0f;
    }
    if (blockIdx.x == 0 && threadIdx.x == 0) {
        // If the buffer is really int32, an int64 read combines two indices ->
        // almost surely out of [0, NE) for some of the first 32 reads.
        const long long* e64 = (const long long*)Ep;
        int ok = 1;
        #pragma unroll 1
        for (int k = 0; k < 32; k++) {
            long long v = e64[k];
            if (v < 0 || v >= (long long)NE) { ok = 0; break; }
        }
        g_mode = ok;
    }
}

// ---------------- K1: scatter-sum + counts (vector RED) ----------------
// One warp per incidence (index loads broadcast), one thread per float4 of d.
__global__ void k_scatter(const float* __restrict__ X,
                          const void* __restrict__ Vp,
                          const void* __restrict__ Ep) {
    int gid = blockIdx.x * 256 + threadIdx.x;        // NI*32 threads
    int inc = gid >> 5;
    int q   = gid & 31;                              // float4 index over d
    int v, e;
    if (g_mode) {
        v = (int)((const long long*)Vp)[inc];
        e = (int)((const long long*)Ep)[inc];
    } else {
        v = ((const int*)Vp)[inc];
        e = ((const int*)Ep)[inc];
    }
    float4 f = *(const float4*)(X + v * D + q * 4);
    float* dst = g_eSum + e * D + q * 4;
    asm volatile("red.global.add.v4.f32 [%0], {%1, %2, %3, %4};"
                 :: "l"(dst), "f"(f.x), "f"(f.y), "f"(f.z), "f"(f.w) : "memory");
    if (q == 0)
        asm volatile("red.global.add.f32 [%0], %1;"
                     :: "l"(&g_eCnt[e]), "f"(1.0f) : "memory");
}

// ---------------- K2: fused GEMM for hX and hEb ----------------
// Rows 0..511   : A = X,                out g_hX  = X @ W1[:, :128].T
// Rows 512..1023: A = eSum/max(cnt,1),  out g_hEb = eX @ W1[:, 128:].T + b1
__global__ void __launch_bounds__(256) k_gemm(const float* __restrict__ X,
                                              const float* __restrict__ W1,
                                              const float* __restrict__ b1) {
    __shared__ float sA[32 * 68];   // [k][row], ld=68
    __shared__ float sB[32 * 68];   // [k][h]
    int tid = threadIdx.x;
    int tx = tid & 15, ty = tid >> 4;
    int h0 = blockIdx.x * 64;
    int r0 = blockIdx.y * 64;
    bool isX = (r0 < NN);
    int koff = isX ? 0 : D;

    float acc[4][4];
    #pragma unroll
    for (int i = 0; i < 4; i++)
        #pragma unroll
        for (int j = 0; j < 4; j++) acc[i][j] = 0.0f;

    for (int k0 = 0; k0 < D; k0 += 32) {
        __syncthreads();
        #pragma unroll
        for (int i = 0; i < 2; i++) {
            int lin = tid + 256 * i;          // 0..511
            int kq  = lin & 7;
            int row = lin >> 3;
            int gr  = r0 + row;
            float4 f;
            if (isX) {
                f = *(const float4*)(X + gr * D + k0 + kq * 4);
            } else {
                f = *(const float4*)(g_eSum + (gr - NN) * D + k0 + kq * 4);
                float c = g_eCnt[gr - NN];
                float s = 1.0f / fmaxf(c, 1.0f);
                f.x *= s; f.y *= s; f.z *= s; f.w *= s;
            }
            sA[(kq * 4 + 0) * 68 + row] = f.x;
            sA[(kq * 4 + 1) * 68 + row] = f.y;
            sA[(kq * 4 + 2) * 68 + row] = f.z;
            sA[(kq * 4 + 3) * 68 + row] = f.w;

            float4 g = *(const float4*)(W1 + (h0 + row) * (2 * D) + koff + k0 + kq * 4);
            sB[(kq * 4 + 0) * 68 + row] = g.x;
            sB[(kq * 4 + 1) * 68 + row] = g.y;
            sB[(kq * 4 + 2) * 68 + row] = g.z;
            sB[(kq * 4 + 3) * 68 + row] = g.w;
        }
        __syncthreads();

        #pragma unroll
        for (int kk = 0; kk < 32; kk++) {
            float4 a4 = *(float4*)&sA[kk * 68 + 4 * ty];
            float4 b4 = *(float4*)&sB[kk * 68 + 4 * tx];
            float a[4] = {a4.x, a4.y, a4.z, a4.w};
            float b[4] = {b4.x, b4.y, b4.z, b4.w};
            #pragma unroll
            for (int i = 0; i < 4; i++)
                #pragma unroll
                for (int j = 0; j < 4; j++)
                    acc[i][j] = fmaf(a[i], b[j], acc[i][j]);
        }
    }

    #pragma unroll
    for (int i = 0; i < 4; i++) {
        int gr = r0 + 4 * ty + i;
        #pragma unroll
        for (int j = 0; j < 4; j++) {
            int h = h0 + 4 * tx + j;
            if (isX) g_hX[gr * H + h] = acc[i][j];
            else     g_hEb[(gr - NN) * H + h] = acc[i][j] + b1[h];
        }
    }
}

// ---------------- K3: fused relu-dot + sigmoid epilogue (f32x2) ----------------
// out[n,m] = clip(sigmoid( sum_h relu(hX[n,h]+hEb[m,h]) * W2[h] + b2 ))
// 32x32 tile per CTA, 256 threads (8 warps), thread tile 2(n) x 2(m).
// Accumulators packed over h-pairs (even-h in lo, odd-h in hi).
__global__ void __launch_bounds__(256) k_epi(const float* __restrict__ W2,
                                             const float* __restrict__ b2,
                                             float* __restrict__ out) {
    __shared__ float sX[32 * 132];  // [n][h], ld=132
    __shared__ float sE[32 * 132];  // [m][h]
    __shared__ float sW[H];
    int tid = threadIdx.x;
    int tx = tid & 15;              // m = m0 + tx (+16)
    int ty = tid >> 4;              // n = n0 + ty (+16)
    int m0 = blockIdx.x * 32;
    int n0 = blockIdx.y * 32;

    if (tid < H) sW[tid] = W2[tid];

    ull acc[2][2];
    #pragma unroll
    for (int i = 0; i < 2; i++)
        #pragma unroll
        for (int j = 0; j < 2; j++) acc[i][j] = 0ULL;

    for (int hc = 0; hc < H; hc += 128) {
        __syncthreads();
        #pragma unroll
        for (int i = 0; i < 8; i++) {
            int lin = tid + 256 * i;          // 0..2047
            int hq = lin & 31;                // float4 index over h
            int r  = (lin >> 5) & 31;         // 0..31
            if (lin < 1024)
                *(float4*)&sX[r * 132 + 4 * hq] =
                    *(const float4*)(g_hX  + (n0 + r) * H + hc + 4 * hq);
            else
                *(float4*)&sE[r * 132 + 4 * hq] =
                    *(const float4*)(g_hEb + (m0 + r) * H + hc + 4 * hq);
        }
        __syncthreads();

        #pragma unroll 4
        for (int h = 0; h < 128; h += 4) {
            float4 w4 = *(float4*)&sW[hc + h];
            ull w2a = pk2(w4.x, w4.y);
            ull w2b = pk2(w4.z, w4.w);

            float4 xa = *(float4*)&sX[ty * 132 + h];
            float4 xb = *(float4*)&sX[(ty + 16) * 132 + h];
            float4 ea = *(float4*)&sE[tx * 132 + h];
            float4 eb = *(float4*)&sE[(tx + 16) * 132 + h];

            ull x2[2][2] = {{pk2(xa.x, xa.y), pk2(xa.z, xa.w)},
                            {pk2(xb.x, xb.y), pk2(xb.z, xb.w)}};
            ull e2[2][2] = {{pk2(ea.x, ea.y), pk2(ea.z, ea.w)},
                            {pk2(eb.x, eb.y), pk2(eb.z, eb.w)}};

            #pragma unroll
            for (int i = 0; i < 2; i++) {
                #pragma unroll
                for (int j = 0; j < 2; j++) {
                    ull t0 = relu2(add2(x2[i][0], e2[j][0]));
                    acc[i][j] = fma2(t0, w2a, acc[i][j]);
                    ull t1 = relu2(add2(x2[i][1], e2[j][1]));
                    acc[i][j] = fma2(t1, w2b, acc[i][j]);
                }
            }
        }
    }

    float b2v = b2[0];
    #pragma unroll
    for (int i = 0; i < 2; i++) {
        int n = n0 + ty + 16 * i;
        #pragma unroll
        for (int j = 0; j < 2; j++) {
            int m = m0 + tx + 16 * j;
            float lg = hsum2(acc[i][j]) + b2v;
            float p = 1.0f / (1.0f + __expf(-lg));
            p = fminf(fmaxf(p, 1e-6f), 1.0f - 1e-6f);
            out[n * NE + m] = p;
        }
    }
}

// ---------------- launch ----------------
extern "C" void kernel_launch(void* const* d_in, const int* in_sizes, int n_in,
                              void* d_out, int out_size) {
    const float* X  = (const float*)d_in[0];
    const void*  V  = d_in[1];
    const void*  E  = d_in[2];
    const float* W1 = (const float*)d_in[3];
    const float* b1 = (const float*)d_in[4];
    const float* W2 = (const float*)d_in[5];
    const float* b2 = (const float*)d_in[6];
    float* out = (float*)d_out;

    k_zero_detect<<<258, 256>>>(E);                           // 258*256 == 512*128 + 512
    k_scatter<<<(NI * 32) / 256, 256>>>(X, V, E);             // 1024 blocks
    k_gemm<<<dim3(H / 64, (NN + NE) / 64), 256>>>(X, W1, b1); // (4,16)
    k_epi<<<dim3(NE / 32, NN / 32), 256>>>(W2, b2, out);      // (16,16)
}

// round 3
// speedup vs baseline: 1.1592x; 1.1073x over previous
#include <cuda_runtime.h>

#define NN 512   // nodes
#define NE 512   // edges
#define D  128   // emb dim
#define H  256   // hidden
#define NI 8192  // incidences

// ---------------- scratch (no allocations allowed) ----------------
__device__ float g_eSum[NE * D];
__device__ float g_eCnt[NE];
__device__ float g_hX [NN * H];
__device__ float g_hEb[NE * H];
__device__ int   g_mode;   // 1 = indices are int64, 0 = int32

typedef unsigned long long ull;

// fused triad on packed f32x2: acc += relu(x + e) * w
// relu done with FMNMX on the pair halves; mov.b64 pack/unpack coalesces away.
__device__ __forceinline__ void triad(ull& acc, ull x, ull e, ull w) {
    asm("{\n\t"
        ".reg .f32 lo, hi;\n\t"
        ".reg .b64 t;\n\t"
        "add.rn.f32x2 t, %1, %2;\n\t"
        "mov.b64 {lo, hi}, t;\n\t"
        "max.f32 lo, lo, 0f00000000;\n\t"
        "max.f32 hi, hi, 0f00000000;\n\t"
        "mov.b64 t, {lo, hi};\n\t"
        "fma.rn.f32x2 %0, t, %3, %0;\n\t"
        "}"
        : "+l"(acc) : "l"(x), "l"(e), "l"(w));
}
__device__ __forceinline__ float hsum2(ull t) {
    float lo, hi;
    asm("mov.b64 {%0, %1}, %2;" : "=f"(lo), "=f"(hi) : "l"(t));
    return lo + hi;
}

// ---------------- K0: zero scratch + detect index dtype ----------------
__global__ void k_zero_detect(const void* __restrict__ Ep) {
    int i = blockIdx.x * 256 + threadIdx.x;          // 258*256 covers 512*128 + 512
    if (i < NE * D) {
        g_eSum[i] = 0.0f;
    } else {
        int j = i - NE * D;
        if (j < NE) g_eCnt[j] = 0.0f;
    }
    if (blockIdx.x == 0 && threadIdx.x == 0) {
        const long long* e64 = (const long long*)Ep;
        int ok = 1;
        #pragma unroll 1
        for (int k = 0; k < 32; k++) {
            long long v = e64[k];
            if (v < 0 || v >= (long long)NE) { ok = 0; break; }
        }
        g_mode = ok;
    }
}

// ---------------- K1: scatter-sum + counts (vector RED) ----------------
__global__ void k_scatter(const float* __restrict__ X,
                          const void* __restrict__ Vp,
                          const void* __restrict__ Ep) {
    int gid = blockIdx.x * 256 + threadIdx.x;        // NI*32 threads
    int inc = gid >> 5;
    int q   = gid & 31;
    int v, e;
    if (g_mode) {
        v = (int)((const long long*)Vp)[inc];
        e = (int)((const long long*)Ep)[inc];
    } else {
        v = ((const int*)Vp)[inc];
        e = ((const int*)Ep)[inc];
    }
    float4 f = *(const float4*)(X + v * D + q * 4);
    float* dst = g_eSum + e * D + q * 4;
    asm volatile("red.global.add.v4.f32 [%0], {%1, %2, %3, %4};"
                 :: "l"(dst), "f"(f.x), "f"(f.y), "f"(f.z), "f"(f.w) : "memory");
    if (q == 0)
        asm volatile("red.global.add.f32 [%0], %1;"
                     :: "l"(&g_eCnt[e]), "f"(1.0f) : "memory");
}

// ---------------- K2: fused GEMM for hX and hEb ----------------
// Rows 0..511   : A = X,                out g_hX  = X @ W1[:, :128].T
// Rows 512..1023: A = eSum/max(cnt,1),  out g_hEb = eX @ W1[:, 128:].T + b1
// Block tile 32 rows x 64 h, grid (4, 32) = 128 CTAs, 256 threads, 2x4/thread.
__global__ void __launch_bounds__(256) k_gemm(const float* __restrict__ X,
                                              const float* __restrict__ W1,
                                              const float* __restrict__ b1) {
    __shared__ float sA[32 * 36];   // [k][row], ld=36
    __shared__ float sB[32 * 68];   // [k][h],  ld=68
    int tid = threadIdx.x;
    int tx = tid & 15, ty = tid >> 4;
    int h0 = blockIdx.x * 64;
    int r0 = blockIdx.y * 32;
    bool isX = (r0 < NN);
    int koff = isX ? 0 : D;

    float acc[2][4];
    #pragma unroll
    for (int i = 0; i < 2; i++)
        #pragma unroll
        for (int j = 0; j < 4; j++) acc[i][j] = 0.0f;

    for (int k0 = 0; k0 < D; k0 += 32) {
        __syncthreads();
        {   // A: 32 rows x 32 k = 256 float4, one per thread
            int kq = tid & 7;
            int r  = tid >> 3;
            int gr = r0 + r;
            float4 f;
            if (isX) {
                f = *(const float4*)(X + gr * D + k0 + kq * 4);
            } else {
                f = *(const float4*)(g_eSum + (gr - NN) * D + k0 + kq * 4);
                float c = g_eCnt[gr - NN];
                float s = 1.0f / fmaxf(c, 1.0f);
                f.x *= s; f.y *= s; f.z *= s; f.w *= s;
            }
            sA[(kq * 4 + 0) * 36 + r] = f.x;
            sA[(kq * 4 + 1) * 36 + r] = f.y;
            sA[(kq * 4 + 2) * 36 + r] = f.z;
            sA[(kq * 4 + 3) * 36 + r] = f.w;
        }
        #pragma unroll
        for (int i = 0; i < 2; i++) {  // B: 64 h x 32 k = 512 float4
            int lin = tid + 256 * i;
            int kq = lin & 7;
            int hr = lin >> 3;          // 0..63
            float4 g = *(const float4*)(W1 + (h0 + hr) * (2 * D) + koff + k0 + kq * 4);
            sB[(kq * 4 + 0) * 68 + hr] = g.x;
            sB[(kq * 4 + 1) * 68 + hr] = g.y;
            sB[(kq * 4 + 2) * 68 + hr] = g.z;
            sB[(kq * 4 + 3) * 68 + hr] = g.w;
        }
        __syncthreads();

        #pragma unroll
        for (int kk = 0; kk < 32; kk++) {
            float2 a2 = *(float2*)&sA[kk * 36 + 2 * ty];
            float4 b4 = *(float4*)&sB[kk * 68 + 4 * tx];
            float a[2] = {a2.x, a2.y};
            float b[4] = {b4.x, b4.y, b4.z, b4.w};
            #pragma unroll
            for (int i = 0; i < 2; i++)
                #pragma unroll
                for (int j = 0; j < 4; j++)
                    acc[i][j] = fmaf(a[i], b[j], acc[i][j]);
        }
    }

    #pragma unroll
    for (int i = 0; i < 2; i++) {
        int gr = r0 + 2 * ty + i;
        #pragma unroll
        for (int j = 0; j < 4; j++) {
            int h = h0 + 4 * tx + j;
            if (isX) g_hX[gr * H + h] = acc[i][j];
            else     g_hEb[(gr - NN) * H + h] = acc[i][j] + b1[h];
        }
    }
}

// ---------------- K3: fused relu-dot + sigmoid epilogue ----------------
// out[n,m] = clip(sigmoid( sum_h relu(hX[n,h]+hEb[m,h]) * W2[h] + b2 ))
// CTA tile 32n x 64m, 256 threads, thread tile 2n x 4m, h in 4 chunks of 64.
// Grid (8, 16) = 128 CTAs. All operands flow through ulonglong2 -> f32x2.
__global__ void __launch_bounds__(256) k_epi(const float* __restrict__ W2,
                                             const float* __restrict__ b2,
                                             float* __restrict__ out) {
    __shared__ float sX[32 * 68];   // [n][h-chunk], ld=68
    __shared__ float sE[64 * 68];   // [m][h-chunk]
    __shared__ float sW[64];
    int tid = threadIdx.x;
    int tx = tid & 15;              // m = m0 + tx + 16*jj
    int ty = tid >> 4;              // n = n0 + ty + 16*ii
    int m0 = blockIdx.x * 64;
    int n0 = blockIdx.y * 32;

    ull acc[2][4];
    #pragma unroll
    for (int i = 0; i < 2; i++)
        #pragma unroll
        for (int j = 0; j < 4; j++) acc[i][j] = 0ULL;

    for (int hc = 0; hc < H; hc += 64) {
        __syncthreads();
        {   // sX: 32 rows x 16 quads = 512 float4 -> 2 per thread
            #pragma unroll
            for (int i = 0; i < 2; i++) {
                int lin = tid + 256 * i;
                int q = lin & 15;
                int r = lin >> 4;       // 0..31
                *(float4*)&sX[r * 68 + 4 * q] =
                    *(const float4*)(g_hX + (n0 + r) * H + hc + 4 * q);
            }
            // sE: 64 rows x 16 quads = 1024 float4 -> 4 per thread
            #pragma unroll
            for (int i = 0; i < 4; i++) {
                int lin = tid + 256 * i;
                int q = lin & 15;
                int r = lin >> 4;       // 0..63
                *(float4*)&sE[r * 68 + 4 * q] =
                    *(const float4*)(g_hEb + (m0 + r) * H + hc + 4 * q);
            }
            if (tid < 16)
                *(float4*)&sW[4 * tid] = *(const float4*)(W2 + hc + 4 * tid);
        }
        __syncthreads();

        #pragma unroll 8
        for (int h = 0; h < 64; h += 4) {
            ulonglong2 W = *(ulonglong2*)&sW[h];               // (w[h],w[h+1]) (w[h+2],w[h+3])
            ulonglong2 Xa[2];
            #pragma unroll
            for (int i = 0; i < 2; i++)
                Xa[i] = *(ulonglong2*)&sX[(ty + 16 * i) * 68 + h];
            ulonglong2 Eb[4];
            #pragma unroll
            for (int j = 0; j < 4; j++)
                Eb[j] = *(ulonglong2*)&sE[(tx + 16 * j) * 68 + h];

            #pragma unroll
            for (int i = 0; i < 2; i++)
                #pragma unroll
                for (int j = 0; j < 4; j++) {
                    triad(acc[i][j], Xa[i].x, Eb[j].x, W.x);
                    triad(acc[i][j], Xa[i].y, Eb[j].y, W.y);
                }
        }
    }

    float b2v = b2[0];
    #pragma unroll
    for (int i = 0; i < 2; i++) {
        int n = n0 + ty + 16 * i;
        #pragma unroll
        for (int j = 0; j < 4; j++) {
            int m = m0 + tx + 16 * j;
            float lg = hsum2(acc[i][j]) + b2v;
            float p = 1.0f / (1.0f + __expf(-lg));
            p = fminf(fmaxf(p, 1e-6f), 1.0f - 1e-6f);
            out[n * NE + m] = p;
        }
    }
}

// ---------------- launch ----------------
extern "C" void kernel_launch(void* const* d_in, const int* in_sizes, int n_in,
                              void* d_out, int out_size) {
    const float* X  = (const float*)d_in[0];
    const void*  V  = d_in[1];
    const void*  E  = d_in[2];
    const float* W1 = (const float*)d_in[3];
    const float* b1 = (const float*)d_in[4];
    const float* W2 = (const float*)d_in[5];
    const float* b2 = (const float*)d_in[6];
    float* out = (float*)d_out;

    k_zero_detect<<<258, 256>>>(E);
    k_scatter<<<(NI * 32) / 256, 256>>>(X, V, E);              // 1024 blocks
    k_gemm<<<dim3(H / 64, (NN + NE) / 32), 256>>>(X, W1, b1);  // (4,32) = 128 CTAs
    k_epi<<<dim3(NE / 64, NN / 32), 256>>>(W2, b2, out);       // (8,16) = 128 CTAs
}